// round 12
// baseline (speedup 1.0000x reference)
#include <cuda_runtime.h>
#include <cuda_fp16.h>

#define NN 50000
#define EE 1600000
#define GG 2000
#define CC 64
#define NEG 0.2f
#define CAP 96                           // padded bucket capacity per dst node

// ---------------- scratch (device globals; no allocation allowed) ----------------
__device__ __half g_xph[NN * 128];       // projected feats fp16 [N,128] (gather)
__device__ float2 g_asrc[NN];            // per-node per-head attn src term
__device__ float2 g_adst[NN];            // per-node per-head attn dst term
__device__ int    g_cnt[NN];             // per-dst fill count (incl. self loop)
__device__ int    g_colp[NN * CAP];      // padded adjacency (ids always in [0,NN))
__device__ float  g_wn[2 * NN * CAP];    // normalized attn weights, planar by head

// ---------------- side stream + events (host-side; created at static init) ------
static cudaStream_t g_s1;
static cudaEvent_t  g_evFork, g_evJoin;
static struct _StreamInit {
    _StreamInit() {
        cudaStreamCreateWithFlags(&g_s1, cudaStreamNonBlocking);
        cudaEventCreateWithFlags(&g_evFork, cudaEventDisableTiming);
        cudaEventCreateWithFlags(&g_evJoin, cudaEventDisableTiming);
    }
} g_streamInit;

// ---------------- 1. projection + attention scalars (fused) ---------------------
// 256 threads, 32 nodes per block. Thread t: output col t&127, node group t>>7.
#define NPB 32
__global__ void proj_kernel(const float* __restrict__ x, const float* __restrict__ W,
                            const float* __restrict__ att_src,
                            const float* __restrict__ att_dst) {
    __shared__ float  WsT[64][132];      // WsT[k][j] = W[j][k]
    __shared__ float4 xs4[NPB][16];      // 32 nodes x 64 floats
    __shared__ float  red[8][16][2];     // per-warp partials [warp][node-in-grp][s/d]
    const int t = threadIdx.x;           // 256 threads
    const int w = t >> 5, lane = t & 31;
    const int col = t & 127;             // output feature column
    const int grp = t >> 7;              // node half (0: nodes 0-15, 1: 16-31)

    for (int idx = t; idx < 8192; idx += 256) {
        WsT[idx & 63][idx >> 6] = W[idx];
    }
    const int n0 = blockIdx.x * NPB;
    for (int idx = t; idx < NPB * 16; idx += 256) {
        int i = idx >> 4, k4 = idx & 15;
        int n = n0 + i;
        xs4[i][k4] = (n < NN) ? reinterpret_cast<const float4*>(x)[n * 16 + k4]
                              : make_float4(0.f, 0.f, 0.f, 0.f);
    }
    __syncthreads();

    float acc[16];
#pragma unroll
    for (int i = 0; i < 16; i++) acc[i] = 0.f;

#pragma unroll
    for (int k4 = 0; k4 < 16; k4++) {
        float w0 = WsT[4 * k4 + 0][col];
        float w1 = WsT[4 * k4 + 1][col];
        float w2 = WsT[4 * k4 + 2][col];
        float w3 = WsT[4 * k4 + 3][col];
#pragma unroll
        for (int i = 0; i < 16; i++) {
            float4 xv = xs4[grp * 16 + i][k4];
            acc[i] += xv.x * w0 + xv.y * w1 + xv.z * w2 + xv.w * w3;
        }
    }
#pragma unroll
    for (int i = 0; i < 16; i++) {
        int n = n0 + grp * 16 + i;
        if (n < NN) g_xph[n * 128 + col] = __float2half(acc[i]);
    }

    // fused attention scalars
    const float av = __ldg(&att_src[col]);
    const float bv = __ldg(&att_dst[col]);
#pragma unroll
    for (int i = 0; i < 16; i++) {
        float p = acc[i] * av;
        float q = acc[i] * bv;
#pragma unroll
        for (int o = 16; o; o >>= 1) {
            p += __shfl_xor_sync(0xffffffffu, p, o);
            q += __shfl_xor_sync(0xffffffffu, q, o);
        }
        if (lane == 0) { red[w][i][0] = p; red[w][i][1] = q; }
    }
    __syncthreads();
    if (t < NPB) {                        // node t of this block
        int n = n0 + t;
        if (n < NN) {
            int wb = (t >> 4) * 4;        // first warp of this node's group
            int i  = t & 15;
            g_asrc[n] = make_float2(red[wb][i][0] + red[wb + 1][i][0],
                                    red[wb + 2][i][0] + red[wb + 3][i][0]);
            g_adst[n] = make_float2(red[wb][i][1] + red[wb + 1][i][1],
                                    red[wb + 2][i][1] + red[wb + 3][i][1]);
        }
    }
}

// ---------------- 2. reset: cnt=1, self loop in slot 0 --------------------------
__global__ void reset_kernel() {
    int i = blockIdx.x * blockDim.x + threadIdx.x;
    if (i < NN) {
        g_cnt[i] = 1;
        g_colp[i * CAP] = i;
    }
}

// ---------------- 3. scatter edges into padded buckets (4 edges/thread) ---------
__global__ void scatter_kernel(const int* __restrict__ ei) {
    int i = (blockIdx.x * blockDim.x + threadIdx.x) * 4;
    if (i >= EE) return;
    int4 s4 = *reinterpret_cast<const int4*>(ei + i);
    int4 d4 = *reinterpret_cast<const int4*>(ei + EE + i);
    int p0 = atomicAdd(&g_cnt[d4.x], 1);
    if (p0 < CAP) g_colp[d4.x * CAP + p0] = s4.x;
    int p1 = atomicAdd(&g_cnt[d4.y], 1);
    if (p1 < CAP) g_colp[d4.y * CAP + p1] = s4.y;
    int p2 = atomicAdd(&g_cnt[d4.z], 1);
    if (p2 < CAP) g_colp[d4.z * CAP + p2] = s4.z;
    int p3 = atomicAdd(&g_cnt[d4.w], 1);
    if (p3 < CAP) g_colp[d4.w * CAP + p3] = s4.w;
}

// ---------------- 4. softmax weights (1 warp / node, lane = edge slot) ----------
// Computes normalized attention weights for both heads at full lane parallelism
// and stores them planar by head. Padding slots (deg..padded-1) get w = 0, so
// the aggregate kernel needs no tail masking at all.
__global__ void weight_kernel() {
    const int node = (blockIdx.x * blockDim.x + threadIdx.x) >> 5;
    const int lane = threadIdx.x & 31;
    if (node >= NN) return;

    int deg = g_cnt[node];
    if (deg > CAP) deg = CAP;
    const int padded = (deg + 3) & ~3;
    const int beg = node * CAP;
    const float2 ad = g_adst[node];

    float w0[3], w1[3];
    float s0 = 0.f, s1 = 0.f;
#pragma unroll
    for (int it = 0; it < 3; it++) {
        int slot = it * 32 + lane;
        float a = 0.f, b = 0.f;
        if (slot < deg) {
            int s = __ldg(&g_colp[beg + slot]);
            float2 as = __ldg(&g_asrc[s]);
            float e0 = as.x + ad.x; e0 = fmaxf(e0, NEG * e0);
            float e1 = as.y + ad.y; e1 = fmaxf(e1, NEG * e1);
            a = __expf(e0);
            b = __expf(e1);
        }
        w0[it] = a; w1[it] = b;
        s0 += a; s1 += b;
    }
#pragma unroll
    for (int o = 16; o; o >>= 1) {
        s0 += __shfl_xor_sync(0xffffffffu, s0, o);
        s1 += __shfl_xor_sync(0xffffffffu, s1, o);
    }
    const float i0 = 1.0f / s0, i1 = 1.0f / s1;
#pragma unroll
    for (int it = 0; it < 3; it++) {
        int slot = it * 32 + lane;
        if (slot < padded) {
            g_wn[beg + slot]            = w0[it] * i0;
            g_wn[NN * CAP + beg + slot] = w1[it] * i1;
        }
    }
}

// ---------------- 5. aggregation (2 dst nodes / warp, pre-normalized weights) ---
// Per 4-edge chunk: 1 int4 (src ids) + 1 float4 (this head's 4 weights) +
// 4 x LDG.128 features + cvt/FFMA. No exp, no wsum, no division, no tail.
__global__ void aggregate_kernel(const float* __restrict__ bias,
                                 float* __restrict__ h_nodes) {
    const int warp = (blockIdx.x * blockDim.x + threadIdx.x) >> 5;
    const int lane = threadIdx.x & 31;
    const int node = warp * 2 + (lane >> 4);     // NN even -> always valid
    if (node >= NN) return;

    const int l16  = lane & 15;
    const int head = l16 >> 3;                   // 0: ch 0-63, 1: ch 64-127
    int deg = g_cnt[node];
    if (deg > CAP) deg = CAP;
    const int beg = node * CAP;                  // multiples of 96 -> 16B aligned
    const float* __restrict__ wplane = g_wn + head * (NN * CAP);

    const uint4* __restrict__ xph = reinterpret_cast<const uint4*>(g_xph); // 16/row

    float a0 = 0.f, a1 = 0.f, a2 = 0.f, a3 = 0.f;
    float a4 = 0.f, a5 = 0.f, a6 = 0.f, a7 = 0.f;

    const int nchunk = (deg + 3) >> 2;
    for (int c = 0; c < nchunk; c++) {
        const int base = beg + c * 4;
        int4   s4 = __ldg(reinterpret_cast<const int4*>(&g_colp[base]));
        float4 wv = __ldg(reinterpret_cast<const float4*>(&wplane[base]));
        uint4 hv0 = __ldg(&xph[s4.x * 16 + l16]);
        uint4 hv1 = __ldg(&xph[s4.y * 16 + l16]);
        uint4 hv2 = __ldg(&xph[s4.z * 16 + l16]);
        uint4 hv3 = __ldg(&xph[s4.w * 16 + l16]);

#define ACC_EDGE(HV, W)                                                        \
        {                                                                      \
            float2 f0 = __half22float2(*reinterpret_cast<__half2*>(&HV.x));    \
            float2 f1 = __half22float2(*reinterpret_cast<__half2*>(&HV.y));    \
            float2 f2 = __half22float2(*reinterpret_cast<__half2*>(&HV.z));    \
            float2 f3 = __half22float2(*reinterpret_cast<__half2*>(&HV.w));    \
            a0 += W * f0.x; a1 += W * f0.y;                                    \
            a2 += W * f1.x; a3 += W * f1.y;                                    \
            a4 += W * f2.x; a5 += W * f2.y;                                    \
            a6 += W * f3.x; a7 += W * f3.y;                                    \
        }
        ACC_EDGE(hv0, wv.x)
        ACC_EDGE(hv1, wv.y)
        ACC_EDGE(hv2, wv.z)
        ACC_EDGE(hv3, wv.w)
#undef ACC_EDGE
    }

    float y[8] = { a0, a1, a2, a3, a4, a5, a6, a7 };

    // head mean: partner lane l16^8 holds the other head's same channel block
#pragma unroll
    for (int i = 0; i < 8; i++)
        y[i] += __shfl_xor_sync(0xffffffffu, y[i], 8);

    if (l16 < 8) {
        float r[8];
#pragma unroll
        for (int i = 0; i < 8; i++)
            r[i] = 0.5f * y[i] + __ldg(&bias[l16 * 8 + i]);
        float4* dst = reinterpret_cast<float4*>(&h_nodes[node * 64 + l16 * 8]);
        dst[0] = make_float4(r[0], r[1], r[2], r[3]);
        dst[1] = make_float4(r[4], r[5], r[6], r[7]);
    }
}

// ---------------- 6. global mean pool: 1 warp / graph, binary search ------------
__global__ void pool_kernel(const int* __restrict__ batch,
                            const float* __restrict__ h_nodes,
                            float* __restrict__ h_graphs) {
    const int g    = (blockIdx.x * blockDim.x + threadIdx.x) >> 5;
    const int lane = threadIdx.x & 31;
    if (g >= GG) return;

    int start = 0, cnt = 0;
    if (lane == 0) {
        int lo = 0, hi = NN;
        while (lo < hi) { int mid = (lo + hi) >> 1; if (batch[mid] < g) lo = mid + 1; else hi = mid; }
        start = lo;
        hi = NN;
        while (lo < hi) { int mid = (lo + hi) >> 1; if (batch[mid] < g + 1) lo = mid + 1; else hi = mid; }
        cnt = lo - start;
    }
    start = __shfl_sync(0xffffffffu, start, 0);
    cnt   = __shfl_sync(0xffffffffu, cnt, 0);

    const int hw  = lane >> 4;
    const int l16 = lane & 15;
    float4 acc = make_float4(0.f, 0.f, 0.f, 0.f);
    for (int n = start + hw; n < start + cnt; n += 2) {
        float4 v = reinterpret_cast<const float4*>(h_nodes)[n * 16 + l16];
        acc.x += v.x; acc.y += v.y; acc.z += v.z; acc.w += v.w;
    }
    acc.x += __shfl_xor_sync(0xffffffffu, acc.x, 16);
    acc.y += __shfl_xor_sync(0xffffffffu, acc.y, 16);
    acc.z += __shfl_xor_sync(0xffffffffu, acc.z, 16);
    acc.w += __shfl_xor_sync(0xffffffffu, acc.w, 16);
    if (lane < 16) {
        float inv = 1.0f / (float)(cnt > 0 ? cnt : 1);
        float4 r = make_float4(acc.x * inv, acc.y * inv, acc.z * inv, acc.w * inv);
        reinterpret_cast<float4*>(h_graphs)[g * 16 + l16] = r;
    }
}

// ---------------- launcher (fork-join: proj ∥ bucket build) ---------------------
extern "C" void kernel_launch(void* const* d_in, const int* in_sizes, int n_in,
                              void* d_out, int out_size) {
    const float* x        = (const float*)d_in[0];
    const int*   ei       = (const int*)  d_in[1];
    const int*   batch    = (const int*)  d_in[2];
    const float* W        = (const float*)d_in[3];
    const float* att_src  = (const float*)d_in[4];
    const float* att_dst  = (const float*)d_in[5];
    const float* bias     = (const float*)d_in[6];
    float* out = (float*)d_out;                    // [N*C | G*C]

    // fork: proj on side stream, bucket build on main stream
    cudaEventRecord(g_evFork, 0);
    cudaStreamWaitEvent(g_s1, g_evFork, 0);
    proj_kernel<<<(NN + NPB - 1) / NPB, 256, 0, g_s1>>>(x, W, att_src, att_dst);
    cudaEventRecord(g_evJoin, g_s1);

    reset_kernel<<<(NN + 255) / 256, 256>>>();
    scatter_kernel<<<(EE / 4 + 255) / 256, 256>>>(ei);

    // join: weight + aggregate need proj output + buckets
    cudaStreamWaitEvent(0, g_evJoin, 0);
    weight_kernel<<<(NN * 32 + 255) / 256, 256>>>();
    aggregate_kernel<<<((NN / 2) * 32 + 255) / 256, 256>>>(bias, out);
    pool_kernel<<<(GG * 32 + 255) / 256, 256>>>(batch, out, out + NN * CC);
}

// round 13
// speedup vs baseline: 1.1053x; 1.1053x over previous
#include <cuda_runtime.h>
#include <cuda_fp16.h>

#define NN 50000
#define EE 1600000
#define GG 2000
#define CC 64
#define NEG 0.2f
#define CAP 96                           // padded bucket capacity per dst node

// ---------------- scratch (device globals; no allocation allowed) ----------------
__device__ __half g_xph[NN * 128];       // projected feats fp16 [N,128] (gather)
__device__ float2 g_asrc[NN];            // per-node per-head attn src term
__device__ float2 g_adst[NN];            // per-node per-head attn dst term
__device__ int    g_cnt[NN];             // per-dst fill count (incl. self loop)
__device__ int    g_colp[NN * CAP];      // padded adjacency (padding slots stay 0)
__device__ float  g_wn[2 * NN * CAP];    // UNnormalized attn weights, planar by head
                                         // (padding slots stay 0 -> no tail logic)

// ---------------- side stream + events (host-side; created at static init) ------
static cudaStream_t g_s1;
static cudaEvent_t  g_evFork, g_evJoin;
static struct _StreamInit {
    _StreamInit() {
        cudaStreamCreateWithFlags(&g_s1, cudaStreamNonBlocking);
        cudaEventCreateWithFlags(&g_evFork, cudaEventDisableTiming);
        cudaEventCreateWithFlags(&g_evJoin, cudaEventDisableTiming);
    }
} g_streamInit;

// ---------------- 1. projection + attention scalars (fused, register-blocked) ---
// 256 threads = 8 warps; warp owns 6 nodes, lane owns 4 output cols (4l..4l+3).
// Per k4: 4 conflict-free LDS.128 of W (reused across 6 nodes) + 6 broadcast
// LDS of x  ->  10 LDS per 96 FFMA (was 20 per 64): FFMA-bound, not smem-bound.
#define PNB 48
__global__ void proj_kernel(const float* __restrict__ x, const float* __restrict__ W,
                            const float* __restrict__ att_src,
                            const float* __restrict__ att_dst) {
    __shared__ float  WsT[64][132];      // [k][j]; 132-pad: 16B-aligned rows,
                                         // low-conflict transpose staging
    __shared__ float4 xs[PNB][16];       // 48 nodes x 64 floats
    const int t = threadIdx.x;
    const int w = t >> 5, lane = t & 31;
    const int n0 = blockIdx.x * PNB;

    for (int idx = t; idx < 8192; idx += 256)
        WsT[idx & 63][idx >> 6] = W[idx];            // coalesced gmem read
    for (int idx = t; idx < PNB * 16; idx += 256) {
        int i = idx >> 4, k4 = idx & 15;
        int n = n0 + i;
        xs[i][k4] = (n < NN) ? reinterpret_cast<const float4*>(x)[n * 16 + k4]
                             : make_float4(0.f, 0.f, 0.f, 0.f);
    }
    __syncthreads();

    const int nb = w * 6;                // warp's first local node
    float acc[6][4];
#pragma unroll
    for (int i = 0; i < 6; i++)
        acc[i][0] = acc[i][1] = acc[i][2] = acc[i][3] = 0.f;

#pragma unroll
    for (int k4 = 0; k4 < 16; k4++) {
        float4 wq0 = *reinterpret_cast<const float4*>(&WsT[4 * k4 + 0][4 * lane]);
        float4 wq1 = *reinterpret_cast<const float4*>(&WsT[4 * k4 + 1][4 * lane]);
        float4 wq2 = *reinterpret_cast<const float4*>(&WsT[4 * k4 + 2][4 * lane]);
        float4 wq3 = *reinterpret_cast<const float4*>(&WsT[4 * k4 + 3][4 * lane]);
#pragma unroll
        for (int i = 0; i < 6; i++) {
            float4 xv = xs[nb + i][k4];              // warp-broadcast LDS
            acc[i][0] += xv.x * wq0.x + xv.y * wq1.x + xv.z * wq2.x + xv.w * wq3.x;
            acc[i][1] += xv.x * wq0.y + xv.y * wq1.y + xv.z * wq2.y + xv.w * wq3.y;
            acc[i][2] += xv.x * wq0.z + xv.y * wq1.z + xv.z * wq2.z + xv.w * wq3.z;
            acc[i][3] += xv.x * wq0.w + xv.y * wq1.w + xv.z * wq2.w + xv.w * wq3.w;
        }
    }

    // store fp16 features: lane covers cols 4l..4l+3 of each node
#pragma unroll
    for (int i = 0; i < 6; i++) {
        int n = n0 + nb + i;
        if (n < NN) {
            __half2 h01 = __floats2half2_rn(acc[i][0], acc[i][1]);
            __half2 h23 = __floats2half2_rn(acc[i][2], acc[i][3]);
            uint2 u;
            u.x = *reinterpret_cast<unsigned int*>(&h01);
            u.y = *reinterpret_cast<unsigned int*>(&h23);
            *reinterpret_cast<uint2*>(&g_xph[n * 128 + 4 * lane]) = u;
        }
    }

    // fused attention scalars: head0 = cols 0-63 (lanes 0-15), head1 = lanes 16-31
    const float4 avq = reinterpret_cast<const float4*>(att_src)[lane];
    const float4 bvq = reinterpret_cast<const float4*>(att_dst)[lane];
#pragma unroll
    for (int i = 0; i < 6; i++) {
        float p = acc[i][0] * avq.x + acc[i][1] * avq.y
                + acc[i][2] * avq.z + acc[i][3] * avq.w;
        float q = acc[i][0] * bvq.x + acc[i][1] * bvq.y
                + acc[i][2] * bvq.z + acc[i][3] * bvq.w;
#pragma unroll
        for (int o = 8; o; o >>= 1) {                // reduce within 16-lane halves
            p += __shfl_xor_sync(0xffffffffu, p, o);
            q += __shfl_xor_sync(0xffffffffu, q, o);
        }
        float p1 = __shfl_sync(0xffffffffu, p, 16);  // head1 sum
        float q1 = __shfl_sync(0xffffffffu, q, 16);
        int n = n0 + nb + i;
        if (lane == 0 && n < NN) {
            g_asrc[n] = make_float2(p, p1);
            g_adst[n] = make_float2(q, q1);
        }
    }
}

// ---------------- 2. reset: cnt=1, self loop in slot 0 --------------------------
__global__ void reset_kernel() {
    int i = blockIdx.x * blockDim.x + threadIdx.x;
    if (i < NN) {
        g_cnt[i] = 1;
        g_colp[i * CAP] = i;
    }
}

// ---------------- 3. scatter edges into padded buckets (4 edges/thread) ---------
__global__ void scatter_kernel(const int* __restrict__ ei) {
    int i = (blockIdx.x * blockDim.x + threadIdx.x) * 4;
    if (i >= EE) return;
    int4 s4 = *reinterpret_cast<const int4*>(ei + i);
    int4 d4 = *reinterpret_cast<const int4*>(ei + EE + i);
    int p0 = atomicAdd(&g_cnt[d4.x], 1);
    if (p0 < CAP) g_colp[d4.x * CAP + p0] = s4.x;
    int p1 = atomicAdd(&g_cnt[d4.y], 1);
    if (p1 < CAP) g_colp[d4.y * CAP + p1] = s4.y;
    int p2 = atomicAdd(&g_cnt[d4.z], 1);
    if (p2 < CAP) g_colp[d4.z * CAP + p2] = s4.z;
    int p3 = atomicAdd(&g_cnt[d4.w], 1);
    if (p3 < CAP) g_colp[d4.w * CAP + p3] = s4.w;
}

// ---------------- 4. attn weights, slot-parallel (thread = 4 slots) -------------
// Full lane parallelism: no warp reduce, no normalization (done in aggregate).
// Threads whose 4-slot group is entirely past deg exit; never-written padding
// slots keep their zero-init value, so aggregate needs no tail masking.
__global__ void weight_kernel() {
    int tid = blockIdx.x * blockDim.x + threadIdx.x;
    int sb = tid * 4;                        // slot base (16B-aligned, CAP%4==0)
    if (sb >= NN * CAP) return;
    int node = tid / (CAP / 4);              // sb / CAP
    int within = sb - node * CAP;
    int deg = g_cnt[node];
    if (deg > CAP) deg = CAP;
    if (within >= deg) return;

    float2 ad = __ldg(&g_adst[node]);
    int4 s4 = *reinterpret_cast<const int4*>(&g_colp[sb]);
    float2 as0 = __ldg(&g_asrc[s4.x]);
    float2 as1 = __ldg(&g_asrc[s4.y]);
    float2 as2 = __ldg(&g_asrc[s4.z]);
    float2 as3 = __ldg(&g_asrc[s4.w]);

    int rem = deg - within;                  // >= 1
    float4 w0, w1;
    float e;
    e = as0.x + ad.x; e = fmaxf(e, NEG * e); w0.x = __expf(e);
    e = as0.y + ad.y; e = fmaxf(e, NEG * e); w1.x = __expf(e);
    e = as1.x + ad.x; e = fmaxf(e, NEG * e); w0.y = (rem > 1) ? __expf(e) : 0.f;
    e = as1.y + ad.y; e = fmaxf(e, NEG * e); w1.y = (rem > 1) ? __expf(e) : 0.f;
    e = as2.x + ad.x; e = fmaxf(e, NEG * e); w0.z = (rem > 2) ? __expf(e) : 0.f;
    e = as2.y + ad.y; e = fmaxf(e, NEG * e); w1.z = (rem > 2) ? __expf(e) : 0.f;
    e = as3.x + ad.x; e = fmaxf(e, NEG * e); w0.w = (rem > 3) ? __expf(e) : 0.f;
    e = as3.y + ad.y; e = fmaxf(e, NEG * e); w1.w = (rem > 3) ? __expf(e) : 0.f;

    *reinterpret_cast<float4*>(&g_wn[sb]) = w0;
    *reinterpret_cast<float4*>(&g_wn[NN * CAP + sb]) = w1;
}

// ---------------- 5. aggregation (2 dst nodes / warp, weights pre-computed) -----
// Per 4-edge chunk: int4 src ids + float4 weights + 4 x LDG.128 features +
// cvt/FFMA + 4 FADD for the softmax denominator. One reciprocal at the end.
__global__ void aggregate_kernel(const float* __restrict__ bias,
                                 float* __restrict__ h_nodes) {
    const int warp = (blockIdx.x * blockDim.x + threadIdx.x) >> 5;
    const int lane = threadIdx.x & 31;
    const int node = warp * 2 + (lane >> 4);     // NN even -> always valid
    if (node >= NN) return;

    const int l16  = lane & 15;
    const int head = l16 >> 3;                   // 0: ch 0-63, 1: ch 64-127
    int deg = g_cnt[node];
    if (deg > CAP) deg = CAP;
    const int beg = node * CAP;                  // multiples of 96 -> 16B aligned
    const float* __restrict__ wplane = g_wn + head * (NN * CAP);

    const uint4* __restrict__ xph = reinterpret_cast<const uint4*>(g_xph); // 16/row

    float a0 = 0.f, a1 = 0.f, a2 = 0.f, a3 = 0.f;
    float a4 = 0.f, a5 = 0.f, a6 = 0.f, a7 = 0.f;
    float ws = 0.f;

    const int nchunk = (deg + 3) >> 2;
    for (int c = 0; c < nchunk; c++) {
        const int base = beg + c * 4;
        int4   s4 = __ldg(reinterpret_cast<const int4*>(&g_colp[base]));
        float4 wv = __ldg(reinterpret_cast<const float4*>(&wplane[base]));
        uint4 hv0 = __ldg(&xph[s4.x * 16 + l16]);
        uint4 hv1 = __ldg(&xph[s4.y * 16 + l16]);
        uint4 hv2 = __ldg(&xph[s4.z * 16 + l16]);
        uint4 hv3 = __ldg(&xph[s4.w * 16 + l16]);

        ws += (wv.x + wv.y) + (wv.z + wv.w);

#define ACC_EDGE(HV, W)                                                        \
        {                                                                      \
            float2 f0 = __half22float2(*reinterpret_cast<__half2*>(&HV.x));    \
            float2 f1 = __half22float2(*reinterpret_cast<__half2*>(&HV.y));    \
            float2 f2 = __half22float2(*reinterpret_cast<__half2*>(&HV.z));    \
            float2 f3 = __half22float2(*reinterpret_cast<__half2*>(&HV.w));    \
            a0 += W * f0.x; a1 += W * f0.y;                                    \
            a2 += W * f1.x; a3 += W * f1.y;                                    \
            a4 += W * f2.x; a5 += W * f2.y;                                    \
            a6 += W * f3.x; a7 += W * f3.y;                                    \
        }
        ACC_EDGE(hv0, wv.x)
        ACC_EDGE(hv1, wv.y)
        ACC_EDGE(hv2, wv.z)
        ACC_EDGE(hv3, wv.w)
#undef ACC_EDGE
    }

    const float inv = 1.0f / ws;                 // softmax denominator (this head)
    float y[8] = { a0 * inv, a1 * inv, a2 * inv, a3 * inv,
                   a4 * inv, a5 * inv, a6 * inv, a7 * inv };

    // head mean: partner lane l16^8 holds the other head's same channel block
#pragma unroll
    for (int i = 0; i < 8; i++)
        y[i] += __shfl_xor_sync(0xffffffffu, y[i], 8);

    if (l16 < 8) {
        float r[8];
#pragma unroll
        for (int i = 0; i < 8; i++)
            r[i] = 0.5f * y[i] + __ldg(&bias[l16 * 8 + i]);
        float4* dst = reinterpret_cast<float4*>(&h_nodes[node * 64 + l16 * 8]);
        dst[0] = make_float4(r[0], r[1], r[2], r[3]);
        dst[1] = make_float4(r[4], r[5], r[6], r[7]);
    }
}

// ---------------- 6. global mean pool: 1 warp / graph, binary search ------------
__global__ void pool_kernel(const int* __restrict__ batch,
                            const float* __restrict__ h_nodes,
                            float* __restrict__ h_graphs) {
    const int g    = (blockIdx.x * blockDim.x + threadIdx.x) >> 5;
    const int lane = threadIdx.x & 31;
    if (g >= GG) return;

    int start = 0, cnt = 0;
    if (lane == 0) {
        int lo = 0, hi = NN;
        while (lo < hi) { int mid = (lo + hi) >> 1; if (batch[mid] < g) lo = mid + 1; else hi = mid; }
        start = lo;
        hi = NN;
        while (lo < hi) { int mid = (lo + hi) >> 1; if (batch[mid] < g + 1) lo = mid + 1; else hi = mid; }
        cnt = lo - start;
    }
    start = __shfl_sync(0xffffffffu, start, 0);
    cnt   = __shfl_sync(0xffffffffu, cnt, 0);

    const int hw  = lane >> 4;
    const int l16 = lane & 15;
    float4 acc = make_float4(0.f, 0.f, 0.f, 0.f);
    for (int n = start + hw; n < start + cnt; n += 2) {
        float4 v = reinterpret_cast<const float4*>(h_nodes)[n * 16 + l16];
        acc.x += v.x; acc.y += v.y; acc.z += v.z; acc.w += v.w;
    }
    acc.x += __shfl_xor_sync(0xffffffffu, acc.x, 16);
    acc.y += __shfl_xor_sync(0xffffffffu, acc.y, 16);
    acc.z += __shfl_xor_sync(0xffffffffu, acc.z, 16);
    acc.w += __shfl_xor_sync(0xffffffffu, acc.w, 16);
    if (lane < 16) {
        float inv = 1.0f / (float)(cnt > 0 ? cnt : 1);
        float4 r = make_float4(acc.x * inv, acc.y * inv, acc.z * inv, acc.w * inv);
        reinterpret_cast<float4*>(h_graphs)[g * 16 + l16] = r;
    }
}

// ---------------- launcher (fork-join: proj ∥ bucket build) ---------------------
extern "C" void kernel_launch(void* const* d_in, const int* in_sizes, int n_in,
                              void* d_out, int out_size) {
    const float* x        = (const float*)d_in[0];
    const int*   ei       = (const int*)  d_in[1];
    const int*   batch    = (const int*)  d_in[2];
    const float* W        = (const float*)d_in[3];
    const float* att_src  = (const float*)d_in[4];
    const float* att_dst  = (const float*)d_in[5];
    const float* bias     = (const float*)d_in[6];
    float* out = (float*)d_out;                    // [N*C | G*C]

    // fork: proj on side stream, bucket build on main stream
    cudaEventRecord(g_evFork, 0);
    cudaStreamWaitEvent(g_s1, g_evFork, 0);
    proj_kernel<<<(NN + PNB - 1) / PNB, 256, 0, g_s1>>>(x, W, att_src, att_dst);
    cudaEventRecord(g_evJoin, g_s1);

    reset_kernel<<<(NN + 255) / 256, 256>>>();
    scatter_kernel<<<(EE / 4 + 255) / 256, 256>>>(ei);

    // join: weight + aggregate need proj output + buckets
    cudaStreamWaitEvent(0, g_evJoin, 0);
    weight_kernel<<<(NN * CAP / 4 + 255) / 256, 256>>>();
    aggregate_kernel<<<((NN / 2) * 32 + 255) / 256, 256>>>(bias, out);
    pool_kernel<<<(GG * 32 + 255) / 256, 256>>>(batch, out, out + NN * CC);
}